// round 15
// baseline (speedup 1.0000x reference)
#include <cuda_runtime.h>
#include <cuda_fp16.h>
#include <cstdint>

#define N_ATOMS 200000
#define OUT_F 256
#define BOND_F 6
#define NSA 9              // slices 0..7 full 64k, slice 8 half (k512..543)
#define TILE_M 64
#define NTH 256
#define NBLOCKS 3127
#define EPSV 1e-5f

// shared memory layout (bytes)
// A fragments: [buf][chunk(4)][mrow(2)][mb(2)][lane(32)] x 16B = 8192 per buf
#define SA_OFF 0
#define SIDX_A 16384       // 320 ints
#define SIDX_B 17664       // 320 ints
#define SSUM_O 18944       // 256 f32
#define SSQ_O  19968       // 256 f32
#define SMEM_TOTAL 20992

// fp16 atom features (padded; tail zeros from static init)
__device__ __align__(16) uint16_t gAtom16[(N_ATOMS + 64) * 256];
// W fragment dump: [g][sub(18)][k0h(2)][ncol(4)][t(8)][lane(32)] x uint2
__device__ __align__(16) uint2 gWf[5 * 18 * 2 * 4 * 8 * 32];
__device__ double g_sum[OUT_F];
__device__ double g_sumsq[OUT_F];
__device__ __align__(16) float g_scale[OUT_F];
__device__ __align__(16) float g_shift[OUT_F];

struct Params {
    const float* atom;
    const float* bond;
    const int* an[5];
    const int* bn[5];
    const float* Wself;
    const float* bias;
    const float* Wdeg[5];
    float* out;
};

__device__ __forceinline__ void mma16816(float* c, const uint32_t* a, uint2 b) {
    asm volatile(
        "mma.sync.aligned.m16n8k16.row.col.f32.f16.f16.f32 "
        "{%0,%1,%2,%3}, {%4,%5,%6,%7}, {%8,%9}, {%0,%1,%2,%3};"
        : "+f"(c[0]), "+f"(c[1]), "+f"(c[2]), "+f"(c[3])
        : "r"(a[0]), "r"(a[1]), "r"(a[2]), "r"(a[3]), "r"(b.x), "r"(b.y));
}

__device__ __forceinline__ uint16_t h16(float x) {
    return __half_as_ushort(__float2half_rn(x));
}
__device__ __forceinline__ void hacc4(uint4& a, uint4 b) {
    __half2* pa = (__half2*)&a;
    __half2* pb = (__half2*)&b;
    pa[0] = __hadd2(pa[0], pb[0]);
    pa[1] = __hadd2(pa[1], pb[1]);
    pa[2] = __hadd2(pa[2], pb[2]);
    pa[3] = __hadd2(pa[3], pb[3]);
}

// ---------------- kernels ----------------

__global__ void zero_stats_kernel() {
    g_sum[threadIdx.x] = 0.0;
    g_sumsq[threadIdx.x] = 0.0;
}

// Convert atom features f32 -> fp16 (8 floats / thread)
__global__ __launch_bounds__(256) void prep_x_kernel(const float* __restrict__ atom) {
    const size_t idx = (size_t)blockIdx.x * 256 + threadIdx.x;  // 8-float unit
    if (idx >= (size_t)N_ATOMS * 32) return;
    const float4* src = (const float4*)atom + idx * 2;
    float4 a = src[0], b = src[1];
    uint4 o;
    o.x = (uint32_t)h16(a.x) | ((uint32_t)h16(a.y) << 16);
    o.y = (uint32_t)h16(a.z) | ((uint32_t)h16(a.w) << 16);
    o.z = (uint32_t)h16(b.x) | ((uint32_t)h16(b.y) << 16);
    o.w = (uint32_t)h16(b.z) | ((uint32_t)h16(b.w) << 16);
    ((uint4*)gAtom16)[idx] = o;
}

// Build the B fragment dump: element i -> exact uint2 a consumer lane loads.
// Wstack rows: [0,256)=W_self, [256,518)=W_deg[g], pad to 576 with zeros.
__global__ void prep_w_kernel(Params p) {
    int i = blockIdx.x * 256 + threadIdx.x;
    if (i >= 5 * 18 * 2 * 4 * 8 * 32) return;
    int lane = i & 31;
    int t    = (i >> 5) & 7;
    int ncol = (i >> 8) & 3;
    int k0h  = (i >> 10) & 1;
    int sg   = i >> 11;               // g*18 + ss
    int ss = sg % 18, g = sg / 18;
    int g8 = lane >> 2, tg = lane & 3;
    int nr = ncol * 64 + t * 8 + g8;
    int kb = ss * 32 + k0h * 16 + 2 * tg;
    float w[4];
    int ks[4] = {kb, kb + 1, kb + 8, kb + 9};
#pragma unroll
    for (int j = 0; j < 4; j++) {
        int k = ks[j];
        float v = 0.f;
        if (k < 256)      v = p.Wself[k * 256 + nr];
        else if (k < 518) v = p.Wdeg[g][(k - 256) * 256 + nr];
        w[j] = v;
    }
    uint2 o;
    o.x = (uint32_t)h16(w[0]) | ((uint32_t)h16(w[1]) << 16);
    o.y = (uint32_t)h16(w[2]) | ((uint32_t)h16(w[3]) << 16);
    gWf[i] = o;
}

// fully-unrolled pairwise neighbor gather: MLP = 2*DEG independent LDGs
template<int DEG>
__device__ __forceinline__ void gatherT(int co, int m, int rowsV,
                                        const int* __restrict__ aidx, uint4 V[2]) {
    V[0] = make_uint4(0, 0, 0, 0);
    V[1] = make_uint4(0, 0, 0, 0);
    if (m >= rowsV) return;
#pragma unroll
    for (int j = 0; j < DEG; j += 2) {
        const uint4* s0 = (const uint4*)(gAtom16 + (size_t)aidx[m * DEG + j] * 256 + co);
        uint4 a0 = s0[0], a1 = s0[1];
        if (j + 1 < DEG) {
            const uint4* s1 = (const uint4*)(gAtom16 + (size_t)aidx[m * DEG + j + 1] * 256 + co);
            uint4 b0 = s1[0], b1 = s1[1];
            hacc4(a0, b0);
            hacc4(a1, b1);
        }
        hacc4(V[0], a0);
        hacc4(V[1], a1);
    }
}

// bond sums (slice 8, k 512..517): only q==0 carries data
template<int DEG>
__device__ __forceinline__ void gatherBondT(const float* __restrict__ bond,
                                            int m, int q, int rowsV,
                                            const int* __restrict__ bidx, uint4 V[2]) {
    V[0] = make_uint4(0, 0, 0, 0);
    V[1] = make_uint4(0, 0, 0, 0);
    if (q != 0 || m >= rowsV) return;
    float2 s0 = {0.f, 0.f}, s1 = {0.f, 0.f}, s2 = {0.f, 0.f};
#pragma unroll
    for (int j = 0; j < DEG; j++) {
        const float2* bp = (const float2*)(bond + (size_t)bidx[m * DEG + j] * BOND_F);
        float2 a = bp[0], b = bp[1], c = bp[2];
        s0.x += a.x; s0.y += a.y;
        s1.x += b.x; s1.y += b.y;
        s2.x += c.x; s2.y += c.y;
    }
    V[0].x = (uint32_t)h16(s0.x) | ((uint32_t)h16(s0.y) << 16);
    V[0].y = (uint32_t)h16(s1.x) | ((uint32_t)h16(s1.y) << 16);
    V[0].z = (uint32_t)h16(s2.x) | ((uint32_t)h16(s2.y) << 16);
}

// scatter gathered 16 cols into the A fragment dump
__device__ __forceinline__ void sts_frag(char* smem, int buf, int m, int q,
                                         const uint4 V[2]) {
    const uint32_t* w = (const uint32_t*)V;  // w[j] = cols {2j, 2j+1}
    const int mrow = m >> 5, mb = (m >> 4) & 1, hs = (m >> 3) & 1, g8 = m & 7;
    char* base = smem + SA_OFF + buf * 8192 + (q * 4 + mrow * 2 + mb) * 512 + hs * 4;
#pragma unroll
    for (int tg = 0; tg < 4; tg++) {
        char* a = base + (g8 * 4 + tg) * 16;
        *(uint32_t*)a       = w[tg];       // slot hs   : (row, k)
        *(uint32_t*)(a + 8) = w[tg + 4];   // slot hs+2 : (row, k+8)
    }
}

__global__ __launch_bounds__(NTH, 2) void fused_gcl_kernel(Params p) {
    extern __shared__ char smem[];
    const int tid = threadIdx.x;
    const int b = blockIdx.x;

    int g, bloc, segStart, segSize;
    if      (b < 313)  { g = 0; bloc = b;        segStart = 0;      segSize = 20000; }
    else if (b < 1251) { g = 1; bloc = b - 313;  segStart = 20000;  segSize = 60000; }
    else if (b < 2189) { g = 2; bloc = b - 1251; segStart = 80000;  segSize = 60000; }
    else if (b < 2814) { g = 3; bloc = b - 2189; segStart = 140000; segSize = 40000; }
    else               { g = 4; bloc = b - 2814; segStart = 180000; segSize = 20000; }
    const int deg    = g + 1;
    const int local0 = bloc * TILE_M;
    const int rowsV  = min(TILE_M, segSize - local0);
    const int r0     = segStart + local0;

    int*   aidx = (int*)(smem + SIDX_A);
    int*   bidx = (int*)(smem + SIDX_B);
    float* ssum = (float*)(smem + SSUM_O);
    float* ssq  = (float*)(smem + SSQ_O);
    ssum[tid] = 0.f;
    ssq[tid]  = 0.f;
    for (int i = tid; i < rowsV * deg; i += NTH) {
        aidx[i] = p.an[g][(size_t)local0 * deg + i];
        bidx[i] = p.bn[g][(size_t)local0 * deg + i];
    }
    __syncthreads();

    const int m = tid >> 2, q = tid & 3;
    const int lane = tid & 31, wid = tid >> 5;
    const int mrow = wid & 1, ncol = wid >> 1;       // 2m x 4n warp grid
    const int g8 = lane >> 2, tg = lane & 3;
    // this warp's B fragment stream base: [g][ss][k0h][ncol] blocks of 256 uint2
    const uint2* wbase = gWf + ((size_t)g * 18 * 2 + 0) * 4 * 256;

    float acc[2][8][4];
#pragma unroll
    for (int mb = 0; mb < 2; mb++)
#pragma unroll
        for (int t = 0; t < 8; t++)
#pragma unroll
            for (int j = 0; j < 4; j++) acc[mb][t][j] = 0.f;

    auto gatherSelf = [&](int s, uint4 V[2]) {
        const uint4* src = (const uint4*)(gAtom16 + (size_t)(r0 + m) * 256 + s * 64 + q * 16);
        V[0] = src[0];
        V[1] = src[1];
    };
    auto gatherN = [&](int s, uint4 V[2]) {
        const int co = (s - 4) * 64 + q * 16;
        switch (deg) {
            case 1: gatherT<1>(co, m, rowsV, aidx, V); break;
            case 2: gatherT<2>(co, m, rowsV, aidx, V); break;
            case 3: gatherT<3>(co, m, rowsV, aidx, V); break;
            case 4: gatherT<4>(co, m, rowsV, aidx, V); break;
            default: gatherT<5>(co, m, rowsV, aidx, V); break;
        }
    };
    auto gatherB = [&](uint4 V[2]) {
        switch (deg) {
            case 1: gatherBondT<1>(p.bond, m, q, rowsV, bidx, V); break;
            case 2: gatherBondT<2>(p.bond, m, q, rowsV, bidx, V); break;
            case 3: gatherBondT<3>(p.bond, m, q, rowsV, bidx, V); break;
            case 4: gatherBondT<4>(p.bond, m, q, rowsV, bidx, V); break;
            default: gatherBondT<5>(p.bond, m, q, rowsV, bidx, V); break;
        }
    };

    uint4 V[2];

    // prologue: A(0) fragments
    gatherSelf(0, V);
    sts_frag(smem, 0, m, q, V);
    __syncthreads();

#pragma unroll 1
    for (int s = 0; s < NSA; s++) {
        const int cur = s & 1, nxt = cur ^ 1;
        const bool more = (s + 1 < NSA);
        if (more) {
            if (s + 1 < 4)      gatherSelf(s + 1, V);
            else if (s + 1 < 8) gatherN(s + 1, V);
            else                gatherB(V);
        }

        const char* A = smem + SA_OFF + cur * 8192;
        const int cmax = (s == 8) ? 2 : 4;
#pragma unroll
        for (int c = 0; c < 4; c++) {
            if (c >= cmax) break;
            // B fragments: warp-contiguous 256B per t-batch from L2-resident dump
            const uint2* bsrc = wbase
                + ((size_t)((s * 2 + (c >> 1)) * 2 + (c & 1)) * 4 + ncol) * 256;
            uint2 bf[8];
#pragma unroll
            for (int t = 0; t < 8; t++)
                bf[t] = __ldg(bsrc + t * 32 + lane);
            // A fragments: one LDS.128 per (mb)
            uint32_t ah[2][4];
#pragma unroll
            for (int mb = 0; mb < 2; mb++) {
                const uint4 av = *(const uint4*)(A + (c * 4 + mrow * 2 + mb) * 512 + lane * 16);
                ah[mb][0] = av.x; ah[mb][1] = av.y;
                ah[mb][2] = av.z; ah[mb][3] = av.w;
            }
#pragma unroll
            for (int t = 0; t < 8; t++) {
                mma16816(acc[0][t], ah[0], bf[t]);
                mma16816(acc[1][t], ah[1], bf[t]);
            }
        }
        if (more) sts_frag(smem, nxt, m, q, V);  // disjoint buffer: pre-barrier safe
        __syncthreads();
    }

    // ---- epilogue: bias + ReLU + store + BN stats ----
#pragma unroll
    for (int mb = 0; mb < 2; mb++) {
        const int rA = mrow * 32 + mb * 16 + g8;
        const bool ok0 = rA < rowsV;
        const bool ok1 = (rA + 8) < rowsV;
        float* out0 = p.out + (size_t)(r0 + rA) * OUT_F;
        float* out1 = out0 + 8 * OUT_F;
#pragma unroll
        for (int t = 0; t < 8; t++) {
            const int col = ncol * 64 + t * 8 + 2 * tg;
            const float b0 = __ldg(p.bias + col);
            const float b1 = __ldg(p.bias + col + 1);
            float v00 = fmaxf(acc[mb][t][0] + b0, 0.f);
            float v01 = fmaxf(acc[mb][t][1] + b1, 0.f);
            float v10 = fmaxf(acc[mb][t][2] + b0, 0.f);
            float v11 = fmaxf(acc[mb][t][3] + b1, 0.f);
            if (ok0) *(float2*)(out0 + col) = make_float2(v00, v01);
            if (ok1) *(float2*)(out1 + col) = make_float2(v10, v11);
            float s0 = (ok0 ? v00 : 0.f) + (ok1 ? v10 : 0.f);
            float s1 = (ok0 ? v01 : 0.f) + (ok1 ? v11 : 0.f);
            float q0 = (ok0 ? v00 * v00 : 0.f) + (ok1 ? v10 * v10 : 0.f);
            float q1 = (ok0 ? v01 * v01 : 0.f) + (ok1 ? v11 * v11 : 0.f);
            atomicAdd(&ssum[col],     s0);
            atomicAdd(&ssum[col + 1], s1);
            atomicAdd(&ssq[col],      q0);
            atomicAdd(&ssq[col + 1],  q1);
        }
    }
    __syncthreads();
    atomicAdd(&g_sum[tid],   (double)ssum[tid]);
    atomicAdd(&g_sumsq[tid], (double)ssq[tid]);
}

__global__ void finalize_stats_kernel(const float* __restrict__ bnw,
                                      const float* __restrict__ bnb) {
    const int c = threadIdx.x;
    double mean = g_sum[c] / (double)N_ATOMS;
    double var  = g_sumsq[c] / (double)N_ATOMS - mean * mean;
    float s = bnw[c] * rsqrtf((float)var + EPSV);
    g_scale[c] = s;
    g_shift[c] = bnb[c] - (float)mean * s;
}

__global__ void apply_bn_kernel(float* __restrict__ out) {
    const size_t i = (size_t)blockIdx.x * blockDim.x + threadIdx.x;  // float4 idx
    float4 v = ((float4*)out)[i];
    const int c4 = (int)(i & 63);
    float4 s = ((const float4*)g_scale)[c4];
    float4 t = ((const float4*)g_shift)[c4];
    v.x = v.x * s.x + t.x;
    v.y = v.y * s.y + t.y;
    v.z = v.z * s.z + t.z;
    v.w = v.w * s.w + t.w;
    ((float4*)out)[i] = v;
}

extern "C" void kernel_launch(void* const* d_in, const int* in_sizes, int n_in,
                              void* d_out, int out_size) {
    Params P;
    P.atom = (const float*)d_in[0];
    P.bond = (const float*)d_in[1];
    const bool interleaved = (in_sizes[2] == in_sizes[3]);
    for (int d = 0; d < 5; d++) {
        if (interleaved) {
            P.an[d] = (const int*)d_in[2 + 2 * d];
            P.bn[d] = (const int*)d_in[3 + 2 * d];
        } else {
            P.an[d] = (const int*)d_in[2 + d];
            P.bn[d] = (const int*)d_in[7 + d];
        }
    }
    P.Wself = (const float*)d_in[12];
    P.bias  = (const float*)d_in[13];
    for (int d = 0; d < 5; d++) P.Wdeg[d] = (const float*)d_in[14 + d];
    const float* bnw = (const float*)d_in[19];
    const float* bnb = (const float*)d_in[20];
    P.out = (float*)d_out;

    cudaFuncSetAttribute(fused_gcl_kernel,
                         cudaFuncAttributeMaxDynamicSharedMemorySize, SMEM_TOTAL);

    zero_stats_kernel<<<1, OUT_F>>>();                  // launch 1
    prep_w_kernel<<<720, 256>>>(P);                     // launch 2
    prep_x_kernel<<<25000, 256>>>(P.atom);              // launch 3
    fused_gcl_kernel<<<NBLOCKS, NTH, SMEM_TOTAL>>>(P);  // launch 4 <- profiled
    finalize_stats_kernel<<<1, OUT_F>>>(bnw, bnb);
    apply_bn_kernel<<<(N_ATOMS * (OUT_F / 4)) / 256, 256>>>((float*)d_out);
}

// round 16
// speedup vs baseline: 1.0412x; 1.0412x over previous
#include <cuda_runtime.h>
#include <cuda_fp16.h>
#include <cstdint>

#define N_ATOMS 200000
#define OUT_F 256
#define BOND_F 6
#define NSA 9              // slices 0..7 full 64k, slice 8 half (k512..543)
#define TILE_M 64
#define NTH 256
#define NBLOCKS 3127
#define EPSV 1e-5f

// shared memory layout (bytes)
#define SA_OFF 0           // A(X): [buf][sub][64][80B] -> buf*10240 + sub*5120
#define SB_OFF 20480       // B(W): [buf][sub][256][80B] -> buf*40960 + sub*20480
#define SIDX_A 102400      // 320 ints
#define SIDX_B 103680      // 320 ints
#define SSUM_O 104960      // 256 f32
#define SSQ_O  105984      // 256 f32
#define SMEM_TOTAL 107008

// fp16 atom features (padded 64 rows for tail-tile overreads; zero-init)
__device__ __align__(16) uint16_t gAtom16[(N_ATOMS + 64) * 256];
// W: [g][sub-slice 0..17][n=256][40] fp16 (fragment-permuted k per 16-chunk)
__device__ __align__(16) uint16_t gW[5 * 18 * 256 * 40];
// fp16 intermediate ReLU(total) — read by apply_bn
__device__ __align__(16) uint16_t gTot16[(size_t)N_ATOMS * 256];
__device__ double g_sum[OUT_F];
__device__ double g_sumsq[OUT_F];
__device__ __align__(16) float g_scale[OUT_F];
__device__ __align__(16) float g_shift[OUT_F];

struct Params {
    const float* atom;
    const float* bond;
    const int* an[5];
    const int* bn[5];
    const float* Wself;
    const float* bias;
    const float* Wdeg[5];
    float* out;
};

__device__ __forceinline__ uint32_t smem_u32(const void* p) {
    uint32_t a;
    asm("{ .reg .u64 t; cvta.to.shared.u64 t, %1; cvt.u32.u64 %0, t; }"
        : "=r"(a) : "l"(p));
    return a;
}

__device__ __forceinline__ void cp16(uint32_t sdst, const void* gsrc) {
    asm volatile("cp.async.cg.shared.global [%0], [%1], 16;"
                 :: "r"(sdst), "l"(__cvta_generic_to_global(gsrc)));
}
#define CP_COMMIT() asm volatile("cp.async.commit_group;" ::: "memory")
#define CP_WAIT0()  asm volatile("cp.async.wait_group 0;" ::: "memory")

__device__ __forceinline__ void mma16816(float* c, const uint32_t* a, uint2 b) {
    asm volatile(
        "mma.sync.aligned.m16n8k16.row.col.f32.f16.f16.f32 "
        "{%0,%1,%2,%3}, {%4,%5,%6,%7}, {%8,%9}, {%0,%1,%2,%3};"
        : "+f"(c[0]), "+f"(c[1]), "+f"(c[2]), "+f"(c[3])
        : "r"(a[0]), "r"(a[1]), "r"(a[2]), "r"(a[3]), "r"(b.x), "r"(b.y));
}

__device__ __forceinline__ uint16_t h16(float x) {
    return __half_as_ushort(__float2half_rn(x));
}
__device__ __forceinline__ void hacc4(uint4& a, uint4 b) {
    __half2* pa = (__half2*)&a;
    __half2* pb = (__half2*)&b;
    pa[0] = __hadd2(pa[0], pb[0]);
    pa[1] = __hadd2(pa[1], pb[1]);
    pa[2] = __hadd2(pa[2], pb[2]);
    pa[3] = __hadd2(pa[3], pb[3]);
}

// ---------------- kernels ----------------

__global__ void zero_stats_kernel() {
    g_sum[threadIdx.x] = 0.0;
    g_sumsq[threadIdx.x] = 0.0;
}

// Convert atom features f32 -> fp16 (8 floats / thread)
__global__ __launch_bounds__(256) void prep_x_kernel(const float* __restrict__ atom) {
    const size_t idx = (size_t)blockIdx.x * 256 + threadIdx.x;  // 8-float unit
    if (idx >= (size_t)N_ATOMS * 32) return;
    const float4* src = (const float4*)atom + idx * 2;
    float4 a = src[0], b = src[1];
    uint4 o;
    o.x = (uint32_t)h16(a.x) | ((uint32_t)h16(a.y) << 16);
    o.y = (uint32_t)h16(a.z) | ((uint32_t)h16(a.w) << 16);
    o.z = (uint32_t)h16(b.x) | ((uint32_t)h16(b.y) << 16);
    o.w = (uint32_t)h16(b.z) | ((uint32_t)h16(b.w) << 16);
    ((uint4*)gAtom16)[idx] = o;
}

// Build transposed, fragment-permuted fp16 W sub-slices (18 x 32k, 80B rows).
__global__ void prep_w_kernel(Params p) {
    int i = blockIdx.x * 256 + threadIdx.x;
    if (i >= 5 * 18 * 32 * 64) return;
    int n4 = i & 63;
    int cc = (i >> 6) & 31;
    int sg = i >> 11;                 // g*18 + sub-slice
    int s = sg % 18, g = sg / 18;
    int k = s * 32 + cc;
    float4 w = make_float4(0.f, 0.f, 0.f, 0.f);
    if (k < 256)      w = ((const float4*)p.Wself)[k * 64 + n4];
    else if (k < 518) w = ((const float4*)p.Wdeg[g])[(k - 256) * 64 + n4];
    int kk = cc & 15, ch = cc >> 4;
    int pos = (kk < 8) ? ((kk >> 1) * 4 + (kk & 1))
                       : (((kk - 8) >> 1) * 4 + 2 + (kk & 1));
    int col = ch * 16 + pos;
    size_t base = (size_t)sg * 256 * 40;
    float wf[4] = {w.x, w.y, w.z, w.w};
#pragma unroll
    for (int c = 0; c < 4; c++)
        gW[base + (size_t)(n4 * 4 + c) * 40 + col] = h16(wf[c]);
}

// fully-unrolled pairwise neighbor gather: MLP = 2*DEG independent LDGs
template<int DEG>
__device__ __forceinline__ void gatherT(int co, int m, int rowsV,
                                        const int* __restrict__ aidx, uint4 V[2]) {
    V[0] = make_uint4(0, 0, 0, 0);
    V[1] = make_uint4(0, 0, 0, 0);
    if (m >= rowsV) return;
#pragma unroll
    for (int j = 0; j < DEG; j += 2) {
        const uint4* s0 = (const uint4*)(gAtom16 + (size_t)aidx[m * DEG + j] * 256 + co);
        uint4 a0 = s0[0], a1 = s0[1];
        if (j + 1 < DEG) {
            const uint4* s1 = (const uint4*)(gAtom16 + (size_t)aidx[m * DEG + j + 1] * 256 + co);
            uint4 b0 = s1[0], b1 = s1[1];
            hacc4(a0, b0);
            hacc4(a1, b1);
        }
        hacc4(V[0], a0);
        hacc4(V[1], a1);
    }
}

// bond sums for slice 8 (k 512..517): only q==0 carries data, others zero-fill
template<int DEG>
__device__ __forceinline__ void gatherBondT(const float* __restrict__ bond,
                                            int m, int q, int rowsV,
                                            const int* __restrict__ bidx, uint4 V[2]) {
    V[0] = make_uint4(0, 0, 0, 0);
    V[1] = make_uint4(0, 0, 0, 0);
    if (q != 0 || m >= rowsV) return;
    float2 s0 = {0.f, 0.f}, s1 = {0.f, 0.f}, s2 = {0.f, 0.f};
#pragma unroll
    for (int j = 0; j < DEG; j++) {
        const float2* bp = (const float2*)(bond + (size_t)bidx[m * DEG + j] * BOND_F);
        float2 a = bp[0], b = bp[1], c = bp[2];
        s0.x += a.x; s0.y += a.y;
        s1.x += b.x; s1.y += b.y;
        s2.x += c.x; s2.y += c.y;
    }
    V[0].x = (uint32_t)h16(s0.x) | ((uint32_t)h16(s0.y) << 16);
    V[0].y = (uint32_t)h16(s1.x) | ((uint32_t)h16(s1.y) << 16);
    V[0].z = (uint32_t)h16(s2.x) | ((uint32_t)h16(s2.y) << 16);
}

__device__ __forceinline__ void sts_x16(char* smem, int buf, int m, int q, const uint4 V[2]) {
    char* base = smem + SA_OFF + buf * 10240 + (q >> 1) * 5120 + m * 80 + (q & 1) * 32;
    *(uint4*)base        = V[0];
    *(uint4*)(base + 16) = V[1];
}

__global__ __launch_bounds__(NTH, 2) void fused_gcl_kernel(Params p) {
    extern __shared__ char smem[];
    const uint32_t sb = smem_u32(smem);
    const int tid = threadIdx.x;
    const int b = blockIdx.x;

    int g, bloc, segStart, segSize;
    if      (b < 313)  { g = 0; bloc = b;        segStart = 0;      segSize = 20000; }
    else if (b < 1251) { g = 1; bloc = b - 313;  segStart = 20000;  segSize = 60000; }
    else if (b < 2189) { g = 2; bloc = b - 1251; segStart = 80000;  segSize = 60000; }
    else if (b < 2814) { g = 3; bloc = b - 2189; segStart = 140000; segSize = 40000; }
    else               { g = 4; bloc = b - 2814; segStart = 180000; segSize = 20000; }
    const int deg    = g + 1;
    const int local0 = bloc * TILE_M;
    const int rowsV  = min(TILE_M, segSize - local0);
    const int r0     = segStart + local0;

    int*   aidx = (int*)(smem + SIDX_A);
    int*   bidx = (int*)(smem + SIDX_B);
    float* ssum = (float*)(smem + SSUM_O);
    float* ssq  = (float*)(smem + SSQ_O);
    ssum[tid] = 0.f;
    ssq[tid]  = 0.f;
    for (int i = tid; i < rowsV * deg; i += NTH) {
        aidx[i] = p.an[g][(size_t)local0 * deg + i];
        bidx[i] = p.bn[g][(size_t)local0 * deg + i];
    }
    __syncthreads();

    const int m = tid >> 2, q = tid & 3;
    const int lane = tid & 31, wid = tid >> 5;
    const int mrow = wid & 1, ncol = wid >> 1;       // 2m x 4n warp grid
    const int g8 = lane >> 2, tg = lane & 3;
    const char* wsrc = (const char*)gW + (size_t)g * 18 * 20480;

    float acc[2][8][4];
#pragma unroll
    for (int mb = 0; mb < 2; mb++)
#pragma unroll
        for (int t = 0; t < 8; t++)
#pragma unroll
            for (int j = 0; j < 4; j++) acc[mb][t][j] = 0.f;

    // issue B copy for A-slice s into buffer buf (subs sub-slices)
    auto copyB = [&](int s, int buf, int subs) {
        for (int sub = 0; sub < subs; sub++) {
            const char* src = wsrc + (size_t)(s * 2 + sub) * 20480;
            uint32_t dst = sb + SB_OFF + buf * 40960 + sub * 20480;
#pragma unroll
            for (int j = 0; j < 5; j++) {
                uint32_t off = (uint32_t)(tid + j * NTH) * 16;
                cp16(dst + off, src + off);
            }
        }
    };
    // issue self-feature cp.async for slice s (<4) into buffer buf
    auto copySelfA = [&](int s, int buf) {
#pragma unroll
        for (int e = 0; e < 2; e++) {
            int id = tid + e * NTH;          // 0..511
            int row = id >> 3, j = id & 7;
            const char* src = (const char*)(gAtom16 + (size_t)(r0 + row) * 256 + s * 64 + j * 8);
            uint32_t dst = sb + SA_OFF + buf * 10240 + (j >> 2) * 5120 + row * 80 + (j & 3) * 16;
            cp16(dst, src);
        }
    };
    auto gatherN = [&](int s, uint4 V[2]) {
        const int co = (s - 4) * 64 + q * 16;
        switch (deg) {
            case 1: gatherT<1>(co, m, rowsV, aidx, V); break;
            case 2: gatherT<2>(co, m, rowsV, aidx, V); break;
            case 3: gatherT<3>(co, m, rowsV, aidx, V); break;
            case 4: gatherT<4>(co, m, rowsV, aidx, V); break;
            default: gatherT<5>(co, m, rowsV, aidx, V); break;
        }
    };
    auto gatherB = [&](uint4 V[2]) {
        switch (deg) {
            case 1: gatherBondT<1>(p.bond, m, q, rowsV, bidx, V); break;
            case 2: gatherBondT<2>(p.bond, m, q, rowsV, bidx, V); break;
            case 3: gatherBondT<3>(p.bond, m, q, rowsV, bidx, V); break;
            case 4: gatherBondT<4>(p.bond, m, q, rowsV, bidx, V); break;
            default: gatherBondT<5>(p.bond, m, q, rowsV, bidx, V); break;
        }
    };

    uint4 V[2];

    // prologue: B(0) + A(0)
    copyB(0, 0, 2);
    copySelfA(0, 0);
    CP_COMMIT();
    CP_WAIT0();
    __syncthreads();

#pragma unroll 1
    for (int s = 0; s < NSA; s++) {
        const int cur = s & 1, nxt = cur ^ 1;
        const bool more = (s + 1 < NSA);
        bool nxtGather = false;
        if (more) {
            copyB(s + 1, nxt, (s + 1 == 8) ? 1 : 2);
            if (s + 1 < 4) {
                copySelfA(s + 1, nxt);
            } else if (s + 1 < 8) {
                nxtGather = true;
                gatherN(s + 1, V);
            } else {
                nxtGather = true;
                gatherB(V);
            }
            CP_COMMIT();
        }

        const char* A = smem + SA_OFF + cur * 10240;
        const char* B = smem + SB_OFF + cur * 40960;
        const int cmax = (s == 8) ? 2 : 4;
#pragma unroll
        for (int c = 0; c < 4; c++) {
            if (c >= cmax) break;
            const char* Asub = A + (c >> 1) * 5120;
            const char* Bsub = B + (c >> 1) * 20480;
            const int k0 = (c & 1) * 16;
            uint32_t ah[2][4];
#pragma unroll
            for (int mb = 0; mb < 2; mb++) {
                const int rA = mrow * 32 + mb * 16 + g8;
                const int o0 = rA * 80 + (k0 + 2 * tg) * 2;
                ah[mb][0] = *(const uint32_t*)(Asub + o0);
                ah[mb][1] = *(const uint32_t*)(Asub + o0 + 640);
                ah[mb][2] = *(const uint32_t*)(Asub + o0 + 16);
                ah[mb][3] = *(const uint32_t*)(Asub + o0 + 656);
            }
            uint2 bf[8];
#pragma unroll
            for (int t = 0; t < 8; t++) {
                const int nr = ncol * 64 + t * 8 + g8;
                bf[t] = *(const uint2*)(Bsub + nr * 80 + k0 * 2 + tg * 8);
            }
#pragma unroll
            for (int t = 0; t < 8; t++) {
                mma16816(acc[0][t], ah[0], bf[t]);
                mma16816(acc[1][t], ah[1], bf[t]);
            }
        }
        if (nxtGather) sts_x16(smem, nxt, m, q, V);  // disjoint buffer: pre-barrier safe
        CP_WAIT0();
        __syncthreads();
    }

    // ---- epilogue: bias + ReLU + fp16 store + BN stats ----
#pragma unroll
    for (int mb = 0; mb < 2; mb++) {
        const int rA = mrow * 32 + mb * 16 + g8;
        const bool ok0 = rA < rowsV;
        const bool ok1 = (rA + 8) < rowsV;
        uint16_t* t0 = gTot16 + (size_t)(r0 + rA) * OUT_F;
        uint16_t* t1 = t0 + 8 * OUT_F;
#pragma unroll
        for (int t = 0; t < 8; t++) {
            const int col = ncol * 64 + t * 8 + 2 * tg;
            const float b0 = __ldg(p.bias + col);
            const float b1 = __ldg(p.bias + col + 1);
            float v00 = fmaxf(acc[mb][t][0] + b0, 0.f);
            float v01 = fmaxf(acc[mb][t][1] + b1, 0.f);
            float v10 = fmaxf(acc[mb][t][2] + b0, 0.f);
            float v11 = fmaxf(acc[mb][t][3] + b1, 0.f);
            if (ok0) *(uint32_t*)(t0 + col) =
                (uint32_t)h16(v00) | ((uint32_t)h16(v01) << 16);
            if (ok1) *(uint32_t*)(t1 + col) =
                (uint32_t)h16(v10) | ((uint32_t)h16(v11) << 16);
            float s0 = (ok0 ? v00 : 0.f) + (ok1 ? v10 : 0.f);
            float s1 = (ok0 ? v01 : 0.f) + (ok1 ? v11 : 0.f);
            float q0 = (ok0 ? v00 * v00 : 0.f) + (ok1 ? v10 * v10 : 0.f);
            float q1 = (ok0 ? v01 * v01 : 0.f) + (ok1 ? v11 * v11 : 0.f);
            atomicAdd(&ssum[col],     s0);
            atomicAdd(&ssum[col + 1], s1);
            atomicAdd(&ssq[col],      q0);
            atomicAdd(&ssq[col + 1],  q1);
        }
    }
    __syncthreads();
    atomicAdd(&g_sum[tid],   (double)ssum[tid]);
    atomicAdd(&g_sumsq[tid], (double)ssq[tid]);
}

__global__ void finalize_stats_kernel(const float* __restrict__ bnw,
                                      const float* __restrict__ bnb) {
    const int c = threadIdx.x;
    double mean = g_sum[c] / (double)N_ATOMS;
    double var  = g_sumsq[c] / (double)N_ATOMS - mean * mean;
    float s = bnw[c] * rsqrtf((float)var + EPSV);
    g_scale[c] = s;
    g_shift[c] = bnb[c] - (float)mean * s;
}

// read fp16 intermediate (8 halves/thread), apply BN, write f32 output
__global__ __launch_bounds__(256) void apply_bn_kernel(float* __restrict__ out) {
    const size_t i = (size_t)blockIdx.x * 256 + threadIdx.x;  // unit of 8 halves
    const uint4 hv = ((const uint4*)gTot16)[i];
    const int c8 = (int)(i & 31);                             // 8-col unit in row
    const float4 s0 = ((const float4*)g_scale)[c8 * 2];
    const float4 s1 = ((const float4*)g_scale)[c8 * 2 + 1];
    const float4 t0 = ((const float4*)g_shift)[c8 * 2];
    const float4 t1 = ((const float4*)g_shift)[c8 * 2 + 1];
    float2 p0 = __half22float2(*(const __half2*)&hv.x);
    float2 p1 = __half22float2(*(const __half2*)&hv.y);
    float2 p2 = __half22float2(*(const __half2*)&hv.z);
    float2 p3 = __half22float2(*(const __half2*)&hv.w);
    float4 o0, o1;
    o0.x = p0.x * s0.x + t0.x;
    o0.y = p0.y * s0.y + t0.y;
    o0.z = p1.x * s0.z + t0.z;
    o0.w = p1.y * s0.w + t0.w;
    o1.x = p2.x * s1.x + t1.x;
    o1.y = p2.y * s1.y + t1.y;
    o1.z = p3.x * s1.z + t1.z;
    o1.w = p3.y * s1.w + t1.w;
    float4* dst = (float4*)(out + i * 8);
    dst[0] = o0;
    dst[1] = o1;
}

extern "C" void kernel_launch(void* const* d_in, const int* in_sizes, int n_in,
                              void* d_out, int out_size) {
    Params P;
    P.atom = (const float*)d_in[0];
    P.bond = (const float*)d_in[1];
    const bool interleaved = (in_sizes[2] == in_sizes[3]);
    for (int d = 0; d < 5; d++) {
        if (interleaved) {
            P.an[d] = (const int*)d_in[2 + 2 * d];
            P.bn[d] = (const int*)d_in[3 + 2 * d];
        } else {
            P.an[d] = (const int*)d_in[2 + d];
            P.bn[d] = (const int*)d_in[7 + d];
        }
    }
    P.Wself = (const float*)d_in[12];
    P.bias  = (const float*)d_in[13];
    for (int d = 0; d < 5; d++) P.Wdeg[d] = (const float*)d_in[14 + d];
    const float* bnw = (const float*)d_in[19];
    const float* bnb = (const float*)d_in[20];
    P.out = (float*)d_out;

    cudaFuncSetAttribute(fused_gcl_kernel,
                         cudaFuncAttributeMaxDynamicSharedMemorySize, SMEM_TOTAL);

    zero_stats_kernel<<<1, OUT_F>>>();                  // launch 1
    prep_w_kernel<<<720, 256>>>(P);                     // launch 2
    prep_x_kernel<<<25000, 256>>>(P.atom);              // launch 3
    fused_gcl_kernel<<<NBLOCKS, NTH, SMEM_TOTAL>>>(P);  // launch 4 <- profiled
    finalize_stats_kernel<<<1, OUT_F>>>(bnw, bnb);
    apply_bn_kernel<<<25000, 256>>>((float*)d_out);
}

// round 17
// speedup vs baseline: 1.0860x; 1.0431x over previous
#include <cuda_runtime.h>
#include <cuda_fp16.h>
#include <cstdint>

#define N_ATOMS 200000
#define OUT_F 256
#define BOND_F 6
#define NSA 9              // slices 0..7 full 64k, slice 8 half (k512..543)
#define TILE_M 64
#define NTH 256
#define NBLOCKS 3127
#define EPSV 1e-5f

// shared memory layout (bytes) — B lives in L2 (gWf), no smem staging
#define SA_OFF 0           // A(X): [buf][sub][64][80B] -> buf*10240 + sub*5120
#define SIDX_A 20480       // 320 ints
#define SIDX_B 21760       // 320 ints
#define SSUM_O 23040       // 256 f32
#define SSQ_O  24064       // 256 f32
#define SMEM_TOTAL 25088

// fp16 atom features (padded 64 rows for tail-tile overreads; zero-init)
__device__ __align__(16) uint16_t gAtom16[(N_ATOMS + 64) * 256];
// B fragment dump in exact consumption order:
// [g][ss(18)][k0h(2)][ncol(4)][t(8)][lane(32)] x uint2  (1.8 MB, L2-resident)
__device__ __align__(16) uint2 gWf[5 * 18 * 2 * 4 * 8 * 32];
// fp16 intermediate ReLU(total) — read by apply_bn
__device__ __align__(16) uint16_t gTot16[(size_t)N_ATOMS * 256];
__device__ double g_sum[OUT_F];
__device__ double g_sumsq[OUT_F];
__device__ __align__(16) float g_scale[OUT_F];
__device__ __align__(16) float g_shift[OUT_F];

struct Params {
    const float* atom;
    const float* bond;
    const int* an[5];
    const int* bn[5];
    const float* Wself;
    const float* bias;
    const float* Wdeg[5];
    float* out;
};

__device__ __forceinline__ uint32_t smem_u32(const void* p) {
    uint32_t a;
    asm("{ .reg .u64 t; cvta.to.shared.u64 t, %1; cvt.u32.u64 %0, t; }"
        : "=r"(a) : "l"(p));
    return a;
}

__device__ __forceinline__ void cp16(uint32_t sdst, const void* gsrc) {
    asm volatile("cp.async.cg.shared.global [%0], [%1], 16;"
                 :: "r"(sdst), "l"(__cvta_generic_to_global(gsrc)));
}
#define CP_COMMIT() asm volatile("cp.async.commit_group;" ::: "memory")
#define CP_WAIT0()  asm volatile("cp.async.wait_group 0;" ::: "memory")

__device__ __forceinline__ void mma16816(float* c, const uint32_t* a, uint2 b) {
    asm volatile(
        "mma.sync.aligned.m16n8k16.row.col.f32.f16.f16.f32 "
        "{%0,%1,%2,%3}, {%4,%5,%6,%7}, {%8,%9}, {%0,%1,%2,%3};"
        : "+f"(c[0]), "+f"(c[1]), "+f"(c[2]), "+f"(c[3])
        : "r"(a[0]), "r"(a[1]), "r"(a[2]), "r"(a[3]), "r"(b.x), "r"(b.y));
}

__device__ __forceinline__ uint16_t h16(float x) {
    return __half_as_ushort(__float2half_rn(x));
}
__device__ __forceinline__ void hacc4(uint4& a, uint4 b) {
    __half2* pa = (__half2*)&a;
    __half2* pb = (__half2*)&b;
    pa[0] = __hadd2(pa[0], pb[0]);
    pa[1] = __hadd2(pa[1], pb[1]);
    pa[2] = __hadd2(pa[2], pb[2]);
    pa[3] = __hadd2(pa[3], pb[3]);
}

// ---------------- kernels ----------------

__global__ void zero_stats_kernel() {
    g_sum[threadIdx.x] = 0.0;
    g_sumsq[threadIdx.x] = 0.0;
}

// Convert atom features f32 -> fp16 (8 floats / thread)
__global__ __launch_bounds__(256) void prep_x_kernel(const float* __restrict__ atom) {
    const size_t idx = (size_t)blockIdx.x * 256 + threadIdx.x;  // 8-float unit
    if (idx >= (size_t)N_ATOMS * 32) return;
    const float4* src = (const float4*)atom + idx * 2;
    float4 a = src[0], b = src[1];
    uint4 o;
    o.x = (uint32_t)h16(a.x) | ((uint32_t)h16(a.y) << 16);
    o.y = (uint32_t)h16(a.z) | ((uint32_t)h16(a.w) << 16);
    o.z = (uint32_t)h16(b.x) | ((uint32_t)h16(b.y) << 16);
    o.w = (uint32_t)h16(b.z) | ((uint32_t)h16(b.w) << 16);
    ((uint4*)gAtom16)[idx] = o;
}

// Build the B fragment dump: element i -> exact uint2 a consumer lane loads.
// Wstack rows: [0,256)=W_self, [256,518)=W_deg[g], pad to 576 with zeros.
__global__ void prep_w_kernel(Params p) {
    int i = blockIdx.x * 256 + threadIdx.x;
    if (i >= 5 * 18 * 2 * 4 * 8 * 32) return;
    int lane = i & 31;
    int t    = (i >> 5) & 7;
    int ncol = (i >> 8) & 3;
    int k0h  = (i >> 10) & 1;
    int sg   = i >> 11;               // g*18 + ss
    int ss = sg % 18, g = sg / 18;
    int g8 = lane >> 2, tg = lane & 3;
    int nr = ncol * 64 + t * 8 + g8;
    int kb = ss * 32 + k0h * 16 + 2 * tg;
    float w[4];
    int ks[4] = {kb, kb + 1, kb + 8, kb + 9};
#pragma unroll
    for (int j = 0; j < 4; j++) {
        int k = ks[j];
        float v = 0.f;
        if (k < 256)      v = p.Wself[k * 256 + nr];
        else if (k < 518) v = p.Wdeg[g][(k - 256) * 256 + nr];
        w[j] = v;
    }
    uint2 o;
    o.x = (uint32_t)h16(w[0]) | ((uint32_t)h16(w[1]) << 16);
    o.y = (uint32_t)h16(w[2]) | ((uint32_t)h16(w[3]) << 16);
    gWf[i] = o;
}

// fully-unrolled pairwise neighbor gather: MLP = 2*DEG independent LDGs
template<int DEG>
__device__ __forceinline__ void gatherT(int co, int m, int rowsV,
                                        const int* __restrict__ aidx, uint4 V[2]) {
    V[0] = make_uint4(0, 0, 0, 0);
    V[1] = make_uint4(0, 0, 0, 0);
    if (m >= rowsV) return;
#pragma unroll
    for (int j = 0; j < DEG; j += 2) {
        const uint4* s0 = (const uint4*)(gAtom16 + (size_t)aidx[m * DEG + j] * 256 + co);
        uint4 a0 = s0[0], a1 = s0[1];
        if (j + 1 < DEG) {
            const uint4* s1 = (const uint4*)(gAtom16 + (size_t)aidx[m * DEG + j + 1] * 256 + co);
            uint4 b0 = s1[0], b1 = s1[1];
            hacc4(a0, b0);
            hacc4(a1, b1);
        }
        hacc4(V[0], a0);
        hacc4(V[1], a1);
    }
}

// bond sums for slice 8 (k 512..517): only q==0 carries data, others zero-fill
template<int DEG>
__device__ __forceinline__ void gatherBondT(const float* __restrict__ bond,
                                            int m, int q, int rowsV,
                                            const int* __restrict__ bidx, uint4 V[2]) {
    V[0] = make_uint4(0, 0, 0, 0);
    V[1] = make_uint4(0, 0, 0, 0);
    if (q != 0 || m >= rowsV) return;
    float2 s0 = {0.f, 0.f}, s1 = {0.f, 0.f}, s2 = {0.f, 0.f};
#pragma unroll
    for (int j = 0; j < DEG; j++) {
        const float2* bp = (const float2*)(bond + (size_t)bidx[m * DEG + j] * BOND_F);
        float2 a = bp[0], b = bp[1], c = bp[2];
        s0.x += a.x; s0.y += a.y;
        s1.x += b.x; s1.y += b.y;
        s2.x += c.x; s2.y += c.y;
    }
    V[0].x = (uint32_t)h16(s0.x) | ((uint32_t)h16(s0.y) << 16);
    V[0].y = (uint32_t)h16(s1.x) | ((uint32_t)h16(s1.y) << 16);
    V[0].z = (uint32_t)h16(s2.x) | ((uint32_t)h16(s2.y) << 16);
}

__device__ __forceinline__ void sts_x16(char* smem, int buf, int m, int q, const uint4 V[2]) {
    char* base = smem + SA_OFF + buf * 10240 + (q >> 1) * 5120 + m * 80 + (q & 1) * 32;
    *(uint4*)base        = V[0];
    *(uint4*)(base + 16) = V[1];
}

__global__ __launch_bounds__(NTH, 2) void fused_gcl_kernel(Params p) {
    extern __shared__ char smem[];
    const uint32_t sb = smem_u32(smem);
    const int tid = threadIdx.x;
    const int b = blockIdx.x;

    int g, bloc, segStart, segSize;
    if      (b < 313)  { g = 0; bloc = b;        segStart = 0;      segSize = 20000; }
    else if (b < 1251) { g = 1; bloc = b - 313;  segStart = 20000;  segSize = 60000; }
    else if (b < 2189) { g = 2; bloc = b - 1251; segStart = 80000;  segSize = 60000; }
    else if (b < 2814) { g = 3; bloc = b - 2189; segStart = 140000; segSize = 40000; }
    else               { g = 4; bloc = b - 2814; segStart = 180000; segSize = 20000; }
    const int deg    = g + 1;
    const int local0 = bloc * TILE_M;
    const int rowsV  = min(TILE_M, segSize - local0);
    const int r0     = segStart + local0;

    int*   aidx = (int*)(smem + SIDX_A);
    int*   bidx = (int*)(smem + SIDX_B);
    float* ssum = (float*)(smem + SSUM_O);
    float* ssq  = (float*)(smem + SSQ_O);
    ssum[tid] = 0.f;
    ssq[tid]  = 0.f;
    for (int i = tid; i < rowsV * deg; i += NTH) {
        aidx[i] = p.an[g][(size_t)local0 * deg + i];
        bidx[i] = p.bn[g][(size_t)local0 * deg + i];
    }
    __syncthreads();

    const int m = tid >> 2, q = tid & 3;
    const int lane = tid & 31, wid = tid >> 5;
    const int mrow = wid & 1, ncol = wid >> 1;       // 2m x 4n warp grid
    const int g8 = lane >> 2, tg = lane & 3;
    // B fragment stream for this (g, ncol): blocks of 256 uint2
    const uint2* wbase = gWf + (size_t)g * (18 * 2 * 4 * 256);

    float acc[2][8][4];
#pragma unroll
    for (int mb = 0; mb < 2; mb++)
#pragma unroll
        for (int t = 0; t < 8; t++)
#pragma unroll
            for (int j = 0; j < 4; j++) acc[mb][t][j] = 0.f;

    // issue self-feature cp.async for slice s (<4) into buffer buf
    auto copySelfA = [&](int s, int buf) {
#pragma unroll
        for (int e = 0; e < 2; e++) {
            int id = tid + e * NTH;          // 0..511
            int row = id >> 3, j = id & 7;
            const char* src = (const char*)(gAtom16 + (size_t)(r0 + row) * 256 + s * 64 + j * 8);
            uint32_t dst = sb + SA_OFF + buf * 10240 + (j >> 2) * 5120 + row * 80 + (j & 3) * 16;
            cp16(dst, src);
        }
    };
    auto gatherN = [&](int s, uint4 V[2]) {
        const int co = (s - 4) * 64 + q * 16;
        switch (deg) {
            case 1: gatherT<1>(co, m, rowsV, aidx, V); break;
            case 2: gatherT<2>(co, m, rowsV, aidx, V); break;
            case 3: gatherT<3>(co, m, rowsV, aidx, V); break;
            case 4: gatherT<4>(co, m, rowsV, aidx, V); break;
            default: gatherT<5>(co, m, rowsV, aidx, V); break;
        }
    };
    auto gatherB = [&](uint4 V[2]) {
        switch (deg) {
            case 1: gatherBondT<1>(p.bond, m, q, rowsV, bidx, V); break;
            case 2: gatherBondT<2>(p.bond, m, q, rowsV, bidx, V); break;
            case 3: gatherBondT<3>(p.bond, m, q, rowsV, bidx, V); break;
            case 4: gatherBondT<4>(p.bond, m, q, rowsV, bidx, V); break;
            default: gatherBondT<5>(p.bond, m, q, rowsV, bidx, V); break;
        }
    };

    uint4 V[2];

    // prologue: A(0) (self, async)
    copySelfA(0, 0);
    CP_COMMIT();
    CP_WAIT0();
    __syncthreads();

#pragma unroll 1
    for (int s = 0; s < NSA; s++) {
        const int cur = s & 1, nxt = cur ^ 1;
        const bool more = (s + 1 < NSA);
        bool nxtGather = false;
        if (more) {
            if (s + 1 < 4) {
                copySelfA(s + 1, nxt);
                CP_COMMIT();
            } else if (s + 1 < 8) {
                nxtGather = true;
                gatherN(s + 1, V);
            } else {
                nxtGather = true;
                gatherB(V);
            }
        }

        const char* A = smem + SA_OFF + cur * 10240;
        const int cmax = (s == 8) ? 2 : 4;
#pragma unroll
        for (int c = 0; c < 4; c++) {
            if (c >= cmax) break;
            const char* Asub = A + (c >> 1) * 5120;
            const int k0 = (c & 1) * 16;
            // B fragments: warp-contiguous 256B batches from L2-resident dump
            const uint2* bsrc = wbase
                + ((size_t)((s * 2 + (c >> 1)) * 2 + (c & 1)) * 4 + ncol) * 256;
            uint2 bf[8];
#pragma unroll
            for (int t = 0; t < 8; t++)
                bf[t] = __ldg(bsrc + t * 32 + lane);
            uint32_t ah[2][4];
#pragma unroll
            for (int mb = 0; mb < 2; mb++) {
                const int rA = mrow * 32 + mb * 16 + g8;
                const int o0 = rA * 80 + (k0 + 2 * tg) * 2;
                ah[mb][0] = *(const uint32_t*)(Asub + o0);
                ah[mb][1] = *(const uint32_t*)(Asub + o0 + 640);
                ah[mb][2] = *(const uint32_t*)(Asub + o0 + 16);
                ah[mb][3] = *(const uint32_t*)(Asub + o0 + 656);
            }
#pragma unroll
            for (int t = 0; t < 8; t++) {
                mma16816(acc[0][t], ah[0], bf[t]);
                mma16816(acc[1][t], ah[1], bf[t]);
            }
        }
        if (nxtGather) sts_x16(smem, nxt, m, q, V);  // disjoint buffer: pre-barrier safe
        if (more && s + 1 < 4) CP_WAIT0();
        __syncthreads();
    }

    // ---- epilogue: bias + ReLU + fp16 store + BN stats ----
#pragma unroll
    for (int mb = 0; mb < 2; mb++) {
        const int rA = mrow * 32 + mb * 16 + g8;
        const bool ok0 = rA < rowsV;
        const bool ok1 = (rA + 8) < rowsV;
        uint16_t* t0 = gTot16 + (size_t)(r0 + rA) * OUT_F;
        uint16_t* t1 = t0 + 8 * OUT_F;
#pragma unroll
        for (int t = 0; t < 8; t++) {
            const int col = ncol * 64 + t * 8 + 2 * tg;
            const float b0 = __ldg(p.bias + col);
            const float b1 = __ldg(p.bias + col + 1);
            float v00 = fmaxf(acc[mb][t][0] + b0, 0.f);
            float v01 = fmaxf(acc[mb][t][1] + b1, 0.f);
            float v10 = fmaxf(acc[mb][t][2] + b0, 0.f);
            float v11 = fmaxf(acc[mb][t][3] + b1, 0.f);
            if (ok0) *(uint32_t*)(t0 + col) =
                (uint32_t)h16(v00) | ((uint32_t)h16(v01) << 16);
            if (ok1) *(uint32_t*)(t1 + col) =
                (uint32_t)h16(v10) | ((uint32_t)h16(v11) << 16);
            float s0 = (ok0 ? v00 : 0.f) + (ok1 ? v10 : 0.f);
            float s1 = (ok0 ? v01 : 0.f) + (ok1 ? v11 : 0.f);
            float q0 = (ok0 ? v00 * v00 : 0.f) + (ok1 ? v10 * v10 : 0.f);
            float q1 = (ok0 ? v01 * v01 : 0.f) + (ok1 ? v11 * v11 : 0.f);
            atomicAdd(&ssum[col],     s0);
            atomicAdd(&ssum[col + 1], s1);
            atomicAdd(&ssq[col],      q0);
            atomicAdd(&ssq[col + 1],  q1);
        }
    }
    __syncthreads();
    atomicAdd(&g_sum[tid],   (double)ssum[tid]);
    atomicAdd(&g_sumsq[tid], (double)ssq[tid]);
}

__global__ void finalize_stats_kernel(const float* __restrict__ bnw,
                                      const float* __restrict__ bnb) {
    const int c = threadIdx.x;
    double mean = g_sum[c] / (double)N_ATOMS;
    double var  = g_sumsq[c] / (double)N_ATOMS - mean * mean;
    float s = bnw[c] * rsqrtf((float)var + EPSV);
    g_scale[c] = s;
    g_shift[c] = bnb[c] - (float)mean * s;
}

// read fp16 intermediate (8 halves/thread), apply BN, write f32 output
__global__ __launch_bounds__(256) void apply_bn_kernel(float* __restrict__ out) {
    const size_t i = (size_t)blockIdx.x * 256 + threadIdx.x;  // unit of 8 halves
    const uint4 hv = ((const uint4*)gTot16)[i];
    const int c8 = (int)(i & 31);                             // 8-col unit in row
    const float4 s0 = ((const float4*)g_scale)[c8 * 2];
    const float4 s1 = ((const float4*)g_scale)[c8 * 2 + 1];
    const float4 t0 = ((const float4*)g_shift)[c8 * 2];
    const float4 t1 = ((const float4*)g_shift)[c8 * 2 + 1];
    float2 p0 = __half22float2(*(const __half2*)&hv.x);
    float2 p1 = __half22float2(*(const __half2*)&hv.y);
    float2 p2 = __half22float2(*(const __half2*)&hv.z);
    float2 p3 = __half22float2(*(const __half2*)&hv.w);
    float4 o0, o1;
    o0.x = p0.x * s0.x + t0.x;
    o0.y = p0.y * s0.y + t0.y;
    o0.z = p1.x * s0.z + t0.z;
    o0.w = p1.y * s0.w + t0.w;
    o1.x = p2.x * s1.x + t1.x;
    o1.y = p2.y * s1.y + t1.y;
    o1.z = p3.x * s1.z + t1.z;
    o1.w = p3.y * s1.w + t1.w;
    float4* dst = (float4*)(out + i * 8);
    dst[0] = o0;
    dst[1] = o1;
}

extern "C" void kernel_launch(void* const* d_in, const int* in_sizes, int n_in,
                              void* d_out, int out_size) {
    Params P;
    P.atom = (const float*)d_in[0];
    P.bond = (const float*)d_in[1];
    const bool interleaved = (in_sizes[2] == in_sizes[3]);
    for (int d = 0; d < 5; d++) {
        if (interleaved) {
            P.an[d] = (const int*)d_in[2 + 2 * d];
            P.bn[d] = (const int*)d_in[3 + 2 * d];
        } else {
            P.an[d] = (const int*)d_in[2 + d];
            P.bn[d] = (const int*)d_in[7 + d];
        }
    }
    P.Wself = (const float*)d_in[12];
    P.bias  = (const float*)d_in[13];
    for (int d = 0; d < 5; d++) P.Wdeg[d] = (const float*)d_in[14 + d];
    const float* bnw = (const float*)d_in[19];
    const float* bnb = (const float*)d_in[20];
    P.out = (float*)d_out;

    cudaFuncSetAttribute(fused_gcl_kernel,
                         cudaFuncAttributeMaxDynamicSharedMemorySize, SMEM_TOTAL);

    zero_stats_kernel<<<1, OUT_F>>>();                  // launch 1
    prep_w_kernel<<<720, 256>>>(P);                     // launch 2
    prep_x_kernel<<<25000, 256>>>(P.atom);              // launch 3
    fused_gcl_kernel<<<NBLOCKS, NTH, SMEM_TOTAL>>>(P);  // launch 4 <- profiled
    finalize_stats_kernel<<<1, OUT_F>>>(bnw, bnb);
    apply_bn_kernel<<<25000, 256>>>((float*)d_out);
}